// round 1
// baseline (speedup 1.0000x reference)
#include <cuda_runtime.h>

#define NN   50000
#define EE   300000
#define PP   200000
#define IND  480
#define HD   256
#define HIDD 128

// ---------------- scratch (device globals: no allocations allowed) ----------
__device__ float g_h[(size_t)NN * HD];     // node features (current layer)
__device__ float g_tmp[(size_t)NN * HD];   // pre-LN GEMM output
__device__ float g_mean[(size_t)NN * HD];  // scatter accumulator -> mean
__device__ float g_deg[NN];
__device__ float g_z1[(size_t)PP * HIDD];
__device__ float g_z2[(size_t)PP * HIDD];

// ---------------- tiled fp32 GEMM ------------------------------------------
// C[M,Nc] = act( A[M,K] @ B[K,Nc] + bias (+ A2@B2 + bias2 if DUAL) )
// FEAT mode: A is the normalized node matrix H[NN,HD]; logical A row p is
//   concat(|H[i_p]-H[j_p]|, H[i_p]*H[j_p]) with K = 2*HD, built on the fly.
// Requires: K % 16 == 0, Nc % 64 == 0.
template <bool RELU, bool DUAL, bool FEAT>
__global__ __launch_bounds__(256) void sgemm_kernel(
    const float* __restrict__ A, const float* __restrict__ B,
    const float* __restrict__ bias,
    const float* __restrict__ A2, const float* __restrict__ B2,
    const float* __restrict__ bias2,
    const int* __restrict__ iidx, const int* __restrict__ jidx,
    float* __restrict__ C, int M, int Nc, int K)
{
    constexpr int BM = 128, BN = 64, BK = 16, TM = 8, TN = 4;
    __shared__ float As[BK][BM + 4];
    __shared__ float Bs[BK][BN];

    const int tid = threadIdx.x;
    const int tx = tid & 15;          // N direction (TN each)
    const int ty = tid >> 4;          // M direction (TM each)
    const int bm = blockIdx.y * BM;
    const int bn = blockIdx.x * BN;

    float acc[TM][TN];
#pragma unroll
    for (int i = 0; i < TM; ++i)
#pragma unroll
        for (int j = 0; j < TN; ++j) acc[i][j] = 0.f;

    const int nParts = DUAL ? 2 : 1;
    for (int part = 0; part < nParts; ++part) {
        const float* Ap = (DUAL && part) ? A2 : A;
        const float* Bp = (DUAL && part) ? B2 : B;
        for (int k0 = 0; k0 < K; k0 += BK) {
            // ---- load A tile (BM x BK), store transposed ----
#pragma unroll
            for (int r = 0; r < 2; ++r) {
                int m   = (tid >> 2) + r * 64;      // 0..127
                int kq  = (tid & 3) * 4;            // 0,4,8,12
                int row = bm + m;
                float4 v = make_float4(0.f, 0.f, 0.f, 0.f);
                if (row < M) {
                    if (FEAT) {
                        int k = k0 + kq;
                        int a = iidx[row], b = jidx[row];
                        if (k < HD) {
                            float4 xa = *(const float4*)(A + (size_t)a * HD + k);
                            float4 xb = *(const float4*)(A + (size_t)b * HD + k);
                            v = make_float4(fabsf(xa.x - xb.x), fabsf(xa.y - xb.y),
                                            fabsf(xa.z - xb.z), fabsf(xa.w - xb.w));
                        } else {
                            int kk = k - HD;
                            float4 xa = *(const float4*)(A + (size_t)a * HD + kk);
                            float4 xb = *(const float4*)(A + (size_t)b * HD + kk);
                            v = make_float4(xa.x * xb.x, xa.y * xb.y,
                                            xa.z * xb.z, xa.w * xb.w);
                        }
                    } else {
                        v = *(const float4*)(Ap + (size_t)row * K + k0 + kq);
                    }
                }
                As[kq + 0][m] = v.x;
                As[kq + 1][m] = v.y;
                As[kq + 2][m] = v.z;
                As[kq + 3][m] = v.w;
            }
            // ---- load B tile (BK x BN) ----
            {
                int kq = tid >> 4;           // 0..15
                int n4 = (tid & 15) * 4;     // 0..60
                float4 v = *(const float4*)(Bp + (size_t)(k0 + kq) * Nc + bn + n4);
                *(float4*)&Bs[kq][n4] = v;
            }
            __syncthreads();
#pragma unroll
            for (int k = 0; k < BK; ++k) {
                float a[TM], b[TN];
#pragma unroll
                for (int i = 0; i < TM; ++i) a[i] = As[k][ty * TM + i];
#pragma unroll
                for (int j = 0; j < TN; ++j) b[j] = Bs[k][tx * TN + j];
#pragma unroll
                for (int i = 0; i < TM; ++i)
#pragma unroll
                    for (int j = 0; j < TN; ++j) acc[i][j] += a[i] * b[j];
            }
            __syncthreads();
        }
    }

#pragma unroll
    for (int i = 0; i < TM; ++i) {
        int row = bm + ty * TM + i;
        if (row >= M) continue;
#pragma unroll
        for (int j = 0; j < TN; ++j) {
            int col = bn + tx * TN + j;
            float v = acc[i][j] + bias[col];
            if (DUAL) v += bias2[col];
            if (RELU) v = fmaxf(v, 0.f);
            C[(size_t)row * Nc + col] = v;
        }
    }
}

// ---------------- degree count ----------------------------------------------
__global__ __launch_bounds__(256) void deg_kernel(const int* __restrict__ dst,
                                                  float* __restrict__ deg)
{
    int e = blockIdx.x * blockDim.x + threadIdx.x;
    if (e < EE) atomicAdd(&deg[dst[e]], 1.f);
}

// ---------------- gather + scatter-add --------------------------------------
// one thread per (edge, 4-float chunk): 64 chunks per edge
__global__ __launch_bounds__(256) void scatter_kernel(
    const int* __restrict__ src, const int* __restrict__ dst,
    const float* __restrict__ h, float* __restrict__ agg)
{
    long long tid = (long long)blockIdx.x * blockDim.x + threadIdx.x;
    if (tid >= (long long)EE * 64) return;
    int e = (int)(tid >> 6);
    int c = (int)(tid & 63) * 4;
    int s = src[e], d = dst[e];
    float4 v = *(const float4*)(h + (size_t)s * HD + c);
    float* o = agg + (size_t)d * HD + c;
    atomicAdd(o + 0, v.x);
    atomicAdd(o + 1, v.y);
    atomicAdd(o + 2, v.z);
    atomicAdd(o + 3, v.w);
}

// ---------------- agg -> mean (divide by clamped degree) --------------------
__global__ __launch_bounds__(256) void meandiv_kernel(float* __restrict__ agg,
                                                      const float* __restrict__ deg)
{
    long long i = (long long)blockIdx.x * blockDim.x + threadIdx.x;
    if (i >= (long long)NN * HD) return;
    agg[i] /= fmaxf(deg[i >> 8], 1.f);   // HD == 256
}

// ---------------- fused ReLU + LayerNorm (warp per row, H=256) --------------
__global__ __launch_bounds__(256) void relu_ln_kernel(
    const float* __restrict__ X, float* __restrict__ Y,
    const float* __restrict__ gamma, const float* __restrict__ beta, int M)
{
    int row = blockIdx.x * 8 + (threadIdx.x >> 5);
    if (row >= M) return;
    int lane = threadIdx.x & 31;
    const float* x = X + (size_t)row * HD;
    float v[8];
    float s = 0.f;
#pragma unroll
    for (int i = 0; i < 8; ++i) {
        v[i] = fmaxf(x[lane + 32 * i], 0.f);
        s += v[i];
    }
#pragma unroll
    for (int o = 16; o; o >>= 1) s += __shfl_xor_sync(0xffffffffu, s, o);
    float mu = s * (1.f / HD);
    float q = 0.f;
#pragma unroll
    for (int i = 0; i < 8; ++i) { float d = v[i] - mu; q += d * d; }
#pragma unroll
    for (int o = 16; o; o >>= 1) q += __shfl_xor_sync(0xffffffffu, q, o);
    float rstd = rsqrtf(q * (1.f / HD) + 1e-5f);
    float* y = Y + (size_t)row * HD;
#pragma unroll
    for (int i = 0; i < 8; ++i) {
        int c = lane + 32 * i;
        y[c] = (v[i] - mu) * rstd * gamma[c] + beta[c];
    }
}

// ---------------- L2 row-normalize (warp per row) ---------------------------
__global__ __launch_bounds__(256) void l2norm_kernel(
    const float* __restrict__ X, float* __restrict__ Y, int M)
{
    int row = blockIdx.x * 8 + (threadIdx.x >> 5);
    if (row >= M) return;
    int lane = threadIdx.x & 31;
    const float* x = X + (size_t)row * HD;
    float v[8];
    float s = 0.f;
#pragma unroll
    for (int i = 0; i < 8; ++i) { v[i] = x[lane + 32 * i]; s += v[i] * v[i]; }
#pragma unroll
    for (int o = 16; o; o >>= 1) s += __shfl_xor_sync(0xffffffffu, s, o);
    float sc = 1.f / fmaxf(sqrtf(s), 1e-12f);
    float* y = Y + (size_t)row * HD;
#pragma unroll
    for (int i = 0; i < 8; ++i) y[lane + 32 * i] = v[i] * sc;
}

// ---------------- final logits: z2[P,128] . W3[128] + b3 (warp per pair) ----
__global__ __launch_bounds__(256) void logits_kernel(
    const float* __restrict__ z2, const float* __restrict__ W3,
    const float* __restrict__ b3, float* __restrict__ out)
{
    int p = blockIdx.x * 8 + (threadIdx.x >> 5);
    if (p >= PP) return;
    int lane = threadIdx.x & 31;
    const float* z = z2 + (size_t)p * HIDD;
    float s = 0.f;
#pragma unroll
    for (int i = 0; i < 4; ++i) {
        int c = lane + 32 * i;
        s += z[c] * W3[c];
    }
#pragma unroll
    for (int o = 16; o; o >>= 1) s += __shfl_xor_sync(0xffffffffu, s, o);
    if (lane == 0) out[p] = s + b3[0];
}

// ---------------- launch ----------------------------------------------------
extern "C" void kernel_launch(void* const* d_in, const int* in_sizes, int n_in,
                              void* d_out, int out_size)
{
    const float* X       = (const float*)d_in[0];
    const int*   edge    = (const int*)d_in[1];
    const int*   i_idx   = (const int*)d_in[2];
    const int*   j_idx   = (const int*)d_in[3];
    const float* W_in    = (const float*)d_in[4];
    const float* b_in    = (const float*)d_in[5];
    const float* Ws_self = (const float*)d_in[6];
    const float* bs_self = (const float*)d_in[7];
    const float* Ws_nei  = (const float*)d_in[8];
    const float* bs_nei  = (const float*)d_in[9];
    const float* gammas  = (const float*)d_in[10];
    const float* betas   = (const float*)d_in[11];
    const float* W1      = (const float*)d_in[12];
    const float* b1      = (const float*)d_in[13];
    const float* W2      = (const float*)d_in[14];
    const float* b2      = (const float*)d_in[15];
    const float* W3      = (const float*)d_in[16];
    const float* b3      = (const float*)d_in[17];

    const int* src = edge;
    const int* dst = edge + EE;

    float *h, *tmp, *mean, *deg, *z1, *z2;
    cudaGetSymbolAddress((void**)&h,    g_h);
    cudaGetSymbolAddress((void**)&tmp,  g_tmp);
    cudaGetSymbolAddress((void**)&mean, g_mean);
    cudaGetSymbolAddress((void**)&deg,  g_deg);
    cudaGetSymbolAddress((void**)&z1,   g_z1);
    cudaGetSymbolAddress((void**)&z2,   g_z2);

    float* outH = (float*)d_out;
    float* outL = outH + (size_t)NN * HD;

    dim3 blk(256);

    // 1) encoder: h = relu(X @ W_in + b_in)
    sgemm_kernel<true, false, false><<<dim3(HD / 64, (NN + 127) / 128), blk>>>(
        X, W_in, b_in, nullptr, nullptr, nullptr, nullptr, nullptr,
        h, NN, HD, IND);

    // 2) degree
    cudaMemsetAsync(deg, 0, NN * sizeof(float));
    deg_kernel<<<(EE + 255) / 256, blk>>>(dst, deg);

    // 3) GNN layers
    for (int l = 0; l < 3; ++l) {
        cudaMemsetAsync(mean, 0, (size_t)NN * HD * sizeof(float));
        scatter_kernel<<<(int)(((long long)EE * 64 + 255) / 256), blk>>>(src, dst, h, mean);
        meandiv_kernel<<<(int)(((long long)NN * HD + 255) / 256), blk>>>(mean, deg);
        sgemm_kernel<false, true, false><<<dim3(HD / 64, (NN + 127) / 128), blk>>>(
            h, Ws_self + (size_t)l * HD * HD, bs_self + (size_t)l * HD,
            mean, Ws_nei + (size_t)l * HD * HD, bs_nei + (size_t)l * HD,
            nullptr, nullptr, tmp, NN, HD, HD);
        relu_ln_kernel<<<(NN + 7) / 8, blk>>>(tmp, h, gammas + (size_t)l * HD,
                                              betas + (size_t)l * HD, NN);
    }

    // 4) H = l2-normalize(h) -> first part of output
    l2norm_kernel<<<(NN + 7) / 8, blk>>>(h, outH, NN);

    // 5) edge head, feat construction fused into GEMM1 A-loader
    sgemm_kernel<true, false, true><<<dim3(HIDD / 64, (PP + 127) / 128), blk>>>(
        outH, W1, b1, nullptr, nullptr, nullptr, i_idx, j_idx,
        z1, PP, HIDD, 2 * HD);
    sgemm_kernel<true, false, false><<<dim3(HIDD / 64, (PP + 127) / 128), blk>>>(
        z1, W2, b2, nullptr, nullptr, nullptr, nullptr, nullptr,
        z2, PP, HIDD, HIDD);
    logits_kernel<<<(PP + 7) / 8, blk>>>(z2, W3, b3, outL);
}

// round 4
// speedup vs baseline: 1.1347x; 1.1347x over previous
#include <cuda_runtime.h>

#define NN   50000
#define EE   300000
#define PP   200000
#define IND  480
#define HD   256
#define HIDD 128

// ---------------- scratch (device globals) ----------------------------------
__device__ float g_h[(size_t)NN * HD];
__device__ float g_tmp[(size_t)NN * HD];
__device__ float g_mean[(size_t)NN * HD];
__device__ float g_z1[(size_t)PP * HIDD];
__device__ float g_z2[(size_t)PP * HIDD];
__device__ int   g_cnt[NN];
__device__ int   g_off[NN + 1];
__device__ int   g_cur[NN];
__device__ int   g_csr[EE];

__device__ __forceinline__ unsigned f2tf(float f) {
    unsigned u;
    asm("cvt.rna.tf32.f32 %0, %1;" : "=r"(u) : "f"(f));
    return u;
}

// split x into tf32 hi + tf32 lo (3xTF32 scheme)
__device__ __forceinline__ void tfsplit(float x, unsigned& hi, unsigned& lo) {
    hi = f2tf(x);
    float hif = __uint_as_float(hi);
    lo = f2tf(x - hif);
}

// ---------------- 3xTF32 tensor-core GEMM -----------------------------------
// C[M,Nc] = act( A@B + bias (+ A2@B2 + bias2 if DUAL) )
// FEAT: logical A row p = concat(|H[i_p]-H[j_p]|, H[i_p]*H[j_p]), K = 2*HD.
// Requires K%16==0, Nc%128==0.
template <bool RELU, bool DUAL, bool FEAT>
__global__ __launch_bounds__(256) void mma_gemm(
    const float* __restrict__ A, const float* __restrict__ B,
    const float* __restrict__ bias,
    const float* __restrict__ A2, const float* __restrict__ B2,
    const float* __restrict__ bias2,
    const int* __restrict__ iidx, const int* __restrict__ jidx,
    float* __restrict__ C, int M, int Nc, int K)
{
    constexpr int BM = 128, BN = 128, BK = 16;
    __shared__ unsigned As[2][BM][BK + 4];   // [hi/lo], pitch 20
    __shared__ unsigned Bs[2][BK][BN + 8];   // [hi/lo], pitch 136

    const int tid  = threadIdx.x;
    const int warp = tid >> 5, lane = tid & 31;
    const int group = lane >> 2, tig = lane & 3;
    const int wm = (warp & 3) * 32, wn = (warp >> 2) * 64;
    const int bm = blockIdx.y * BM, bn = blockIdx.x * BN;

    float c[2][8][4] = {};

    const int nParts = DUAL ? 2 : 1;
    for (int part = 0; part < nParts; ++part) {
        const float* Ap = (DUAL && part) ? A2 : A;
        const float* Bp = (DUAL && part) ? B2 : B;
        for (int k0 = 0; k0 < K; k0 += BK) {
            // ---- A tile (BM x BK): 8 floats per thread ----
            {
                int m = tid >> 1, kq = (tid & 1) * 8;
                int row = bm + m;
                float vv[8];
#pragma unroll
                for (int q = 0; q < 8; ++q) vv[q] = 0.f;
                if (row < M) {
                    if (FEAT) {
                        int ia = iidx[row], jb = jidx[row];
                        const float* Ha = A + (size_t)ia * HD;
                        const float* Hb = A + (size_t)jb * HD;
                        int k = k0 + kq;
#pragma unroll
                        for (int q = 0; q < 2; ++q) {
                            int kk = k + q * 4;
                            float4 r;
                            if (kk < HD) {
                                float4 xa = *(const float4*)(Ha + kk);
                                float4 xb = *(const float4*)(Hb + kk);
                                r = make_float4(fabsf(xa.x - xb.x), fabsf(xa.y - xb.y),
                                                fabsf(xa.z - xb.z), fabsf(xa.w - xb.w));
                            } else {
                                float4 xa = *(const float4*)(Ha + kk - HD);
                                float4 xb = *(const float4*)(Hb + kk - HD);
                                r = make_float4(xa.x * xb.x, xa.y * xb.y,
                                                xa.z * xb.z, xa.w * xb.w);
                            }
                            vv[q * 4 + 0] = r.x; vv[q * 4 + 1] = r.y;
                            vv[q * 4 + 2] = r.z; vv[q * 4 + 3] = r.w;
                        }
                    } else {
                        const float* p = Ap + (size_t)row * K + k0 + kq;
                        float4 v0 = *(const float4*)p;
                        float4 v1 = *(const float4*)(p + 4);
                        vv[0] = v0.x; vv[1] = v0.y; vv[2] = v0.z; vv[3] = v0.w;
                        vv[4] = v1.x; vv[5] = v1.y; vv[6] = v1.z; vv[7] = v1.w;
                    }
                }
#pragma unroll
                for (int q = 0; q < 8; ++q) {
                    unsigned hi, lo;
                    tfsplit(vv[q], hi, lo);
                    As[0][m][kq + q] = hi;
                    As[1][m][kq + q] = lo;
                }
            }
            // ---- B tile (BK x BN): 8 floats per thread ----
            {
                int kr = tid >> 4, n8 = (tid & 15) * 8;
                const float* p = Bp + (size_t)(k0 + kr) * Nc + bn + n8;
                float4 v0 = *(const float4*)p;
                float4 v1 = *(const float4*)(p + 4);
                float vv[8] = {v0.x, v0.y, v0.z, v0.w, v1.x, v1.y, v1.z, v1.w};
#pragma unroll
                for (int q = 0; q < 8; ++q) {
                    unsigned hi, lo;
                    tfsplit(vv[q], hi, lo);
                    Bs[0][kr][n8 + q] = hi;
                    Bs[1][kr][n8 + q] = lo;
                }
            }
            __syncthreads();
#pragma unroll
            for (int ks = 0; ks < BK; ks += 8) {
                unsigned afh[2][4], afl[2][4], bfh[8][2], bfl[8][2];
#pragma unroll
                for (int i = 0; i < 2; ++i) {
                    int r = wm + i * 16 + group;
                    afh[i][0] = As[0][r][ks + tig];
                    afh[i][1] = As[0][r + 8][ks + tig];
                    afh[i][2] = As[0][r][ks + tig + 4];
                    afh[i][3] = As[0][r + 8][ks + tig + 4];
                    afl[i][0] = As[1][r][ks + tig];
                    afl[i][1] = As[1][r + 8][ks + tig];
                    afl[i][2] = As[1][r][ks + tig + 4];
                    afl[i][3] = As[1][r + 8][ks + tig + 4];
                }
#pragma unroll
                for (int j = 0; j < 8; ++j) {
                    int nc_ = wn + j * 8 + group;
                    bfh[j][0] = Bs[0][ks + tig][nc_];
                    bfh[j][1] = Bs[0][ks + tig + 4][nc_];
                    bfl[j][0] = Bs[1][ks + tig][nc_];
                    bfl[j][1] = Bs[1][ks + tig + 4][nc_];
                }
#pragma unroll
                for (int i = 0; i < 2; ++i)
#pragma unroll
                    for (int j = 0; j < 8; ++j) {
                        // hi * hi
                        asm volatile(
                            "mma.sync.aligned.m16n8k8.row.col.f32.tf32.tf32.f32 "
                            "{%0,%1,%2,%3},{%4,%5,%6,%7},{%8,%9},{%0,%1,%2,%3};"
                            : "+f"(c[i][j][0]), "+f"(c[i][j][1]),
                              "+f"(c[i][j][2]), "+f"(c[i][j][3])
                            : "r"(afh[i][0]), "r"(afh[i][1]), "r"(afh[i][2]), "r"(afh[i][3]),
                              "r"(bfh[j][0]), "r"(bfh[j][1]));
                        // lo * hi
                        asm volatile(
                            "mma.sync.aligned.m16n8k8.row.col.f32.tf32.tf32.f32 "
                            "{%0,%1,%2,%3},{%4,%5,%6,%7},{%8,%9},{%0,%1,%2,%3};"
                            : "+f"(c[i][j][0]), "+f"(c[i][j][1]),
                              "+f"(c[i][j][2]), "+f"(c[i][j][3])
                            : "r"(afl[i][0]), "r"(afl[i][1]), "r"(afl[i][2]), "r"(afl[i][3]),
                              "r"(bfh[j][0]), "r"(bfh[j][1]));
                        // hi * lo
                        asm volatile(
                            "mma.sync.aligned.m16n8k8.row.col.f32.tf32.tf32.f32 "
                            "{%0,%1,%2,%3},{%4,%5,%6,%7},{%8,%9},{%0,%1,%2,%3};"
                            : "+f"(c[i][j][0]), "+f"(c[i][j][1]),
                              "+f"(c[i][j][2]), "+f"(c[i][j][3])
                            : "r"(afh[i][0]), "r"(afh[i][1]), "r"(afh[i][2]), "r"(afh[i][3]),
                              "r"(bfl[j][0]), "r"(bfl[j][1]));
                    }
            }
            __syncthreads();
        }
    }
    // ---- epilogue ----
#pragma unroll
    for (int i = 0; i < 2; ++i) {
        int r0 = bm + wm + i * 16 + group;
#pragma unroll
        for (int j = 0; j < 8; ++j) {
            int col = bn + wn + j * 8 + tig * 2;
            float bb0 = bias[col], bb1 = bias[col + 1];
            if (DUAL) { bb0 += bias2[col]; bb1 += bias2[col + 1]; }
            if (r0 < M) {
                float v0 = c[i][j][0] + bb0, v1 = c[i][j][1] + bb1;
                if (RELU) { v0 = fmaxf(v0, 0.f); v1 = fmaxf(v1, 0.f); }
                C[(size_t)r0 * Nc + col] = v0;
                C[(size_t)r0 * Nc + col + 1] = v1;
            }
            if (r0 + 8 < M) {
                float v2 = c[i][j][2] + bb0, v3 = c[i][j][3] + bb1;
                if (RELU) { v2 = fmaxf(v2, 0.f); v3 = fmaxf(v3, 0.f); }
                C[(size_t)(r0 + 8) * Nc + col] = v2;
                C[(size_t)(r0 + 8) * Nc + col + 1] = v3;
            }
        }
    }
}

// ---------------- CSR build --------------------------------------------------
__global__ __launch_bounds__(256) void count_kernel(const int* __restrict__ dst,
                                                    int* __restrict__ cnt)
{
    int e = blockIdx.x * blockDim.x + threadIdx.x;
    if (e < EE) atomicAdd(&cnt[dst[e]], 1);
}

__global__ __launch_bounds__(1024) void scan_kernel(const int* __restrict__ cnt,
                                                    int* __restrict__ off,
                                                    int* __restrict__ cur)
{
    __shared__ int sh[1024];
    __shared__ int carry;
    int t = threadIdx.x;
    if (t == 0) carry = 0;
    __syncthreads();
    for (int base = 0; base < NN; base += 1024) {
        int i = base + t;
        int v = (i < NN) ? cnt[i] : 0;
        sh[t] = v;
        __syncthreads();
        for (int o = 1; o < 1024; o <<= 1) {
            int x = (t >= o) ? sh[t - o] : 0;
            __syncthreads();
            sh[t] += x;
            __syncthreads();
        }
        int excl = sh[t] - v;
        if (i < NN) { off[i] = carry + excl; cur[i] = carry + excl; }
        __syncthreads();
        if (t == 0) carry += sh[1023];
        __syncthreads();
    }
    if (t == 0) off[NN] = carry;
}

__global__ __launch_bounds__(256) void fill_kernel(const int* __restrict__ src,
                                                   const int* __restrict__ dst,
                                                   int* __restrict__ cur,
                                                   int* __restrict__ csr)
{
    int e = blockIdx.x * blockDim.x + threadIdx.x;
    if (e < EE) {
        int d = dst[e];
        int pos = atomicAdd(&cur[d], 1);
        csr[pos] = src[e];
    }
}

// ---------------- neighbor mean (warp per node, CSR gather) ------------------
__global__ __launch_bounds__(256) void agg_kernel(
    const int* __restrict__ off, const int* __restrict__ csr,
    const float* __restrict__ h, float* __restrict__ mean)
{
    int n = blockIdx.x * 8 + (threadIdx.x >> 5);
    if (n >= NN) return;
    int lane = threadIdx.x & 31;
    int s0 = off[n], s1 = off[n + 1];
    float4 a0 = make_float4(0.f, 0.f, 0.f, 0.f), a1 = a0;
    for (int e = s0; e < s1; ++e) {
        int s = csr[e];
        const float4* hp = (const float4*)(h + (size_t)s * HD);
        float4 v0 = hp[lane], v1 = hp[lane + 32];
        a0.x += v0.x; a0.y += v0.y; a0.z += v0.z; a0.w += v0.w;
        a1.x += v1.x; a1.y += v1.y; a1.z += v1.z; a1.w += v1.w;
    }
    float inv = 1.f / (float)max(s1 - s0, 1);
    a0.x *= inv; a0.y *= inv; a0.z *= inv; a0.w *= inv;
    a1.x *= inv; a1.y *= inv; a1.z *= inv; a1.w *= inv;
    float4* mp = (float4*)(mean + (size_t)n * HD);
    mp[lane] = a0;
    mp[lane + 32] = a1;
}

// ---------------- fused ReLU + LayerNorm (warp per row, H=256) ---------------
__global__ __launch_bounds__(256) void relu_ln_kernel(
    const float* __restrict__ X, float* __restrict__ Y,
    const float* __restrict__ gamma, const float* __restrict__ beta, int M)
{
    int row = blockIdx.x * 8 + (threadIdx.x >> 5);
    if (row >= M) return;
    int lane = threadIdx.x & 31;
    const float* x = X + (size_t)row * HD;
    float v[8];
    float s = 0.f;
#pragma unroll
    for (int i = 0; i < 8; ++i) { v[i] = fmaxf(x[lane + 32 * i], 0.f); s += v[i]; }
#pragma unroll
    for (int o = 16; o; o >>= 1) s += __shfl_xor_sync(0xffffffffu, s, o);
    float mu = s * (1.f / HD);
    float q = 0.f;
#pragma unroll
    for (int i = 0; i < 8; ++i) { float d = v[i] - mu; q += d * d; }
#pragma unroll
    for (int o = 16; o; o >>= 1) q += __shfl_xor_sync(0xffffffffu, q, o);
    float rstd = rsqrtf(q * (1.f / HD) + 1e-5f);
    float* y = Y + (size_t)row * HD;
#pragma unroll
    for (int i = 0; i < 8; ++i) {
        int c = lane + 32 * i;
        y[c] = (v[i] - mu) * rstd * gamma[c] + beta[c];
    }
}

// ---------------- L2 row-normalize ------------------------------------------
__global__ __launch_bounds__(256) void l2norm_kernel(
    const float* __restrict__ X, float* __restrict__ Y, int M)
{
    int row = blockIdx.x * 8 + (threadIdx.x >> 5);
    if (row >= M) return;
    int lane = threadIdx.x & 31;
    const float* x = X + (size_t)row * HD;
    float v[8];
    float s = 0.f;
#pragma unroll
    for (int i = 0; i < 8; ++i) { v[i] = x[lane + 32 * i]; s += v[i] * v[i]; }
#pragma unroll
    for (int o = 16; o; o >>= 1) s += __shfl_xor_sync(0xffffffffu, s, o);
    float sc = 1.f / fmaxf(sqrtf(s), 1e-12f);
    float* y = Y + (size_t)row * HD;
#pragma unroll
    for (int i = 0; i < 8; ++i) y[lane + 32 * i] = v[i] * sc;
}

// ---------------- final logits ----------------------------------------------
__global__ __launch_bounds__(256) void logits_kernel(
    const float* __restrict__ z2, const float* __restrict__ W3,
    const float* __restrict__ b3, float* __restrict__ out)
{
    int p = blockIdx.x * 8 + (threadIdx.x >> 5);
    if (p >= PP) return;
    int lane = threadIdx.x & 31;
    const float* z = z2 + (size_t)p * HIDD;
    float s = 0.f;
#pragma unroll
    for (int i = 0; i < 4; ++i) { int c = lane + 32 * i; s += z[c] * W3[c]; }
#pragma unroll
    for (int o = 16; o; o >>= 1) s += __shfl_xor_sync(0xffffffffu, s, o);
    if (lane == 0) out[p] = s + b3[0];
}

// ---------------- launch ----------------------------------------------------
extern "C" void kernel_launch(void* const* d_in, const int* in_sizes, int n_in,
                              void* d_out, int out_size)
{
    const float* X       = (const float*)d_in[0];
    const int*   edge    = (const int*)d_in[1];
    const int*   i_idx   = (const int*)d_in[2];
    const int*   j_idx   = (const int*)d_in[3];
    const float* W_in    = (const float*)d_in[4];
    const float* b_in    = (const float*)d_in[5];
    const float* Ws_self = (const float*)d_in[6];
    const float* bs_self = (const float*)d_in[7];
    const float* Ws_nei  = (const float*)d_in[8];
    const float* bs_nei  = (const float*)d_in[9];
    const float* gammas  = (const float*)d_in[10];
    const float* betas   = (const float*)d_in[11];
    const float* W1      = (const float*)d_in[12];
    const float* b1      = (const float*)d_in[13];
    const float* W2      = (const float*)d_in[14];
    const float* b2      = (const float*)d_in[15];
    const float* W3      = (const float*)d_in[16];
    const float* b3      = (const float*)d_in[17];

    const int* src = edge;
    const int* dst = edge + EE;

    float *h, *tmp, *mean, *z1, *z2;
    int *cnt, *off, *cur, *csr;
    cudaGetSymbolAddress((void**)&h,    g_h);
    cudaGetSymbolAddress((void**)&tmp,  g_tmp);
    cudaGetSymbolAddress((void**)&mean, g_mean);
    cudaGetSymbolAddress((void**)&z1,   g_z1);
    cudaGetSymbolAddress((void**)&z2,   g_z2);
    cudaGetSymbolAddress((void**)&cnt,  g_cnt);
    cudaGetSymbolAddress((void**)&off,  g_off);
    cudaGetSymbolAddress((void**)&cur,  g_cur);
    cudaGetSymbolAddress((void**)&csr,  g_csr);

    float* outH = (float*)d_out;
    float* outL = outH + (size_t)NN * HD;

    dim3 blk(256);

    // 1) encoder: h = relu(X @ W_in + b_in)
    mma_gemm<true, false, false><<<dim3(HD / 128, (NN + 127) / 128), blk>>>(
        X, W_in, b_in, nullptr, nullptr, nullptr, nullptr, nullptr,
        h, NN, HD, IND);

    // 2) CSR build
    cudaMemsetAsync(cnt, 0, NN * sizeof(int));
    count_kernel<<<(EE + 255) / 256, blk>>>(dst, cnt);
    scan_kernel<<<1, 1024>>>(cnt, off, cur);
    fill_kernel<<<(EE + 255) / 256, blk>>>(src, dst, cur, csr);

    // 3) GNN layers
    for (int l = 0; l < 3; ++l) {
        agg_kernel<<<(NN + 7) / 8, blk>>>(off, csr, h, mean);
        mma_gemm<false, true, false><<<dim3(HD / 128, (NN + 127) / 128), blk>>>(
            h, Ws_self + (size_t)l * HD * HD, bs_self + (size_t)l * HD,
            mean, Ws_nei + (size_t)l * HD * HD, bs_nei + (size_t)l * HD,
            nullptr, nullptr, tmp, NN, HD, HD);
        relu_ln_kernel<<<(NN + 7) / 8, blk>>>(tmp, h, gammas + (size_t)l * HD,
                                              betas + (size_t)l * HD, NN);
    }

    // 4) H = l2-normalize(h)
    l2norm_kernel<<<(NN + 7) / 8, blk>>>(h, outH, NN);

    // 5) edge head (feat fused into GEMM1 A-loader)
    mma_gemm<true, false, true><<<dim3(HIDD / 128, (PP + 127) / 128), blk>>>(
        outH, W1, b1, nullptr, nullptr, nullptr, i_idx, j_idx,
        z1, PP, HIDD, 2 * HD);
    mma_gemm<true, false, false><<<dim3(HIDD / 128, (PP + 127) / 128), blk>>>(
        z1, W2, b2, nullptr, nullptr, nullptr, nullptr, nullptr,
        z2, PP, HIDD, HIDD);
    logits_kernel<<<(PP + 7) / 8, blk>>>(z2, W3, b3, outL);
}